// round 1
// baseline (speedup 1.0000x reference)
#include <cuda_runtime.h>
#include <cuda_bf16.h>
#include <math.h>

// ---------------------------------------------------------------------------
// GritLM pooling: masked segment mean over tokens + L2 normalize per sequence.
// Inputs (metadata order):
//   d_in[0] : float32 hidden_states [TOTAL, D]
//   d_in[1] : int32   prompt_lens   [B]
//   d_in[2] : int32   instruction_lens [B]
// Output: float32 [B, D]
// ---------------------------------------------------------------------------

#define TSPLIT 16
#define MAX_B 64
#define MAX_D 8192
// Partial-sum scratch: TSPLIT * MAX_B * MAX_D floats = 16*64*8192*4 = 32 MB.
// Static device allocation (no runtime allocs allowed).
__device__ float g_part[(size_t)TSPLIT * MAX_B * MAX_D];

// ---------------------------------------------------------------------------
// Kernel 1: partial masked column sums.
// grid: (ceil(D/1024), B, TSPLIT), block: 256 threads.
// Each thread owns a float4 column strip; accumulates rows
// [start + r0, start + r1) with r < instruction_len rows excluded.
// ---------------------------------------------------------------------------
__global__ __launch_bounds__(256, 8)
void pool_partial_kernel(const float* __restrict__ hs,
                         const int* __restrict__ plen,
                         const int* __restrict__ ilen,
                         int B, int D)
{
    const int b     = blockIdx.y;
    const int split = blockIdx.z;
    const int c0    = blockIdx.x * 1024 + threadIdx.x * 4;

    // starts = exclusive prefix sum of prompt_lens (B is tiny)
    long long start = 0;
    for (int i = 0; i < b; i++) start += (long long)plen[i];
    const int len  = plen[b];
    const int inst = ilen[b];

    const int chunk = (len + TSPLIT - 1) / TSPLIT;
    int r0 = split * chunk;
    int r1 = r0 + chunk; if (r1 > len) r1 = len;
    if (r0 < inst) r0 = inst;        // mask instruction tokens

    float4 acc = make_float4(0.f, 0.f, 0.f, 0.f);

    if (c0 < D && r0 < r1) {
        const float* base = hs + (start + (long long)r0) * (long long)D + c0;
        const long long stride = D;
        int r = r0;
        // 4x unroll for MLP
        for (; r + 3 < r1; r += 4) {
            float4 v0 = *(const float4*)(base);
            float4 v1 = *(const float4*)(base + stride);
            float4 v2 = *(const float4*)(base + 2 * stride);
            float4 v3 = *(const float4*)(base + 3 * stride);
            acc.x += v0.x + v1.x + v2.x + v3.x;
            acc.y += v0.y + v1.y + v2.y + v3.y;
            acc.z += v0.z + v1.z + v2.z + v3.z;
            acc.w += v0.w + v1.w + v2.w + v3.w;
            base += 4 * stride;
        }
        for (; r < r1; r++) {
            float4 v = *(const float4*)(base);
            acc.x += v.x; acc.y += v.y; acc.z += v.z; acc.w += v.w;
            base += stride;
        }
    }

    if (c0 < D) {
        float* p = &g_part[((size_t)split * B + b) * (size_t)D + c0];
        *(float4*)p = acc;
    }
}

// ---------------------------------------------------------------------------
// Kernel 2: reduce TSPLIT partials -> mean, write to out.
// One thread per float4 of the [B, D] output.
// ---------------------------------------------------------------------------
__global__ void reduce_mean_kernel(const int* __restrict__ plen,
                                   const int* __restrict__ ilen,
                                   float* __restrict__ out,
                                   int B, int D)
{
    const int idx = blockIdx.x * blockDim.x + threadIdx.x;  // float4 index
    const int per_row = D / 4;
    if (idx >= B * per_row) return;
    const int b = idx / per_row;
    const int c = (idx - b * per_row) * 4;

    float4 s = make_float4(0.f, 0.f, 0.f, 0.f);
#pragma unroll
    for (int t = 0; t < TSPLIT; t++) {
        const float4 v = *(const float4*)&g_part[((size_t)t * B + b) * (size_t)D + c];
        s.x += v.x; s.y += v.y; s.z += v.z; s.w += v.w;
    }
    const float cnt = (float)(plen[b] - ilen[b]);
    const float inv = 1.0f / cnt;
    s.x *= inv; s.y *= inv; s.z *= inv; s.w *= inv;
    *(float4*)(out + (size_t)b * D + c) = s;
}

// ---------------------------------------------------------------------------
// Kernel 3: in-place L2 normalize each [D] row of out. One block per row.
// ---------------------------------------------------------------------------
__global__ void l2norm_kernel(float* __restrict__ out, int D)
{
    const int b = blockIdx.x;
    float* row = out + (size_t)b * D;

    float ss = 0.f;
    for (int c = threadIdx.x * 4; c < D; c += blockDim.x * 4) {
        float4 v = *(const float4*)(row + c);
        ss += v.x * v.x + v.y * v.y + v.z * v.z + v.w * v.w;
    }
    // block reduce
    __shared__ float sm[32];
    for (int off = 16; off > 0; off >>= 1)
        ss += __shfl_down_sync(0xFFFFFFFFu, ss, off);
    const int lane = threadIdx.x & 31, wid = threadIdx.x >> 5;
    if (lane == 0) sm[wid] = ss;
    __syncthreads();
    const int nwarps = (blockDim.x + 31) >> 5;
    if (wid == 0) {
        float v = (lane < nwarps) ? sm[lane] : 0.f;
        for (int off = 16; off > 0; off >>= 1)
            v += __shfl_down_sync(0xFFFFFFFFu, v, off);
        if (lane == 0) sm[0] = v;
    }
    __syncthreads();
    float norm = sqrtf(sm[0]);
    norm = fmaxf(norm, 1e-12f);
    const float inv = 1.0f / norm;

    for (int c = threadIdx.x * 4; c < D; c += blockDim.x * 4) {
        float4 v = *(const float4*)(row + c);
        v.x *= inv; v.y *= inv; v.z *= inv; v.w *= inv;
        *(float4*)(row + c) = v;
    }
}

// ---------------------------------------------------------------------------
extern "C" void kernel_launch(void* const* d_in, const int* in_sizes, int n_in,
                              void* d_out, int out_size)
{
    const float* hs   = (const float*)d_in[0];
    const int*   plen = (const int*)d_in[1];
    const int*   ilen = (const int*)d_in[2];
    float*       out  = (float*)d_out;

    const int B = in_sizes[1];
    const int D = out_size / B;   // 4096

    // Kernel 1: partial sums
    dim3 grid1((D + 1023) / 1024, B, TSPLIT);
    pool_partial_kernel<<<grid1, 256>>>(hs, plen, ilen, B, D);

    // Kernel 2: reduce + mean
    const int total4 = B * (D / 4);
    reduce_mean_kernel<<<(total4 + 255) / 256, 256>>>(plen, ilen, out, B, D);

    // Kernel 3: L2 normalize
    l2norm_kernel<<<B, 256>>>(out, D);
}

// round 2
// speedup vs baseline: 1.0231x; 1.0231x over previous
#include <cuda_runtime.h>
#include <cuda_bf16.h>
#include <math.h>

// ---------------------------------------------------------------------------
// GritLM pooling: masked segment mean over tokens + L2 normalize per sequence.
// Inputs (metadata order):
//   d_in[0] : float32 hidden_states [TOTAL, D]
//   d_in[1] : int32   prompt_lens   [B]
//   d_in[2] : int32   instruction_lens [B]
// Output: float32 [B, D]
//
// Stage 1: masked partial column sums (memory-wall bound, ~6.3 TB/s).
// Stage 2: fused reduce + mean + L2 normalize (one kernel, B blocks).
// ---------------------------------------------------------------------------

#define TSPLIT 16
#define MAX_B 64
#define MAX_D 8192
// Partial-sum scratch (static device allocation; runtime allocs forbidden).
__device__ float g_part[(size_t)TSPLIT * MAX_B * MAX_D];

// ---------------------------------------------------------------------------
// Kernel 1: partial masked column sums.
// grid: (ceil(D/1024), B, TSPLIT), block: 256 threads.
// Each thread owns a float4 column strip; accumulates rows
// [start + r0, start + r1) with r < instruction_len rows excluded.
// ---------------------------------------------------------------------------
__global__ __launch_bounds__(256, 8)
void pool_partial_kernel(const float* __restrict__ hs,
                         const int* __restrict__ plen,
                         const int* __restrict__ ilen,
                         int B, int D)
{
    const int b     = blockIdx.y;
    const int split = blockIdx.z;
    const int c0    = blockIdx.x * 1024 + threadIdx.x * 4;

    // starts = exclusive prefix sum of prompt_lens (B is tiny)
    long long start = 0;
    for (int i = 0; i < b; i++) start += (long long)plen[i];
    const int len  = plen[b];
    const int inst = ilen[b];

    const int chunk = (len + TSPLIT - 1) / TSPLIT;
    int r0 = split * chunk;
    int r1 = r0 + chunk; if (r1 > len) r1 = len;
    if (r0 < inst) r0 = inst;        // mask instruction tokens

    float4 acc = make_float4(0.f, 0.f, 0.f, 0.f);

    if (c0 < D && r0 < r1) {
        const float* base = hs + (start + (long long)r0) * (long long)D + c0;
        const long long stride = D;
        int r = r0;
        // 4x row unroll -> MLP=4 independent LDG.128 per thread
        for (; r + 3 < r1; r += 4) {
            float4 v0 = *(const float4*)(base);
            float4 v1 = *(const float4*)(base + stride);
            float4 v2 = *(const float4*)(base + 2 * stride);
            float4 v3 = *(const float4*)(base + 3 * stride);
            acc.x += v0.x + v1.x + v2.x + v3.x;
            acc.y += v0.y + v1.y + v2.y + v3.y;
            acc.z += v0.z + v1.z + v2.z + v3.z;
            acc.w += v0.w + v1.w + v2.w + v3.w;
            base += 4 * stride;
        }
        for (; r < r1; r++) {
            float4 v = *(const float4*)(base);
            acc.x += v.x; acc.y += v.y; acc.z += v.z; acc.w += v.w;
            base += stride;
        }
    }

    if (c0 < D) {
        float* p = &g_part[((size_t)split * B + b) * (size_t)D + c0];
        *(float4*)p = acc;
    }
}

// ---------------------------------------------------------------------------
// Kernel 2 (fused): reduce TSPLIT partials -> mean -> L2 normalize -> out.
// One block per sequence; blockDim.x == D/4 (one float4 per thread, D<=4096).
// Partials were just written by kernel 1, so these reads hit L2.
// ---------------------------------------------------------------------------
__global__ __launch_bounds__(1024)
void mean_norm_kernel(const int* __restrict__ plen,
                      const int* __restrict__ ilen,
                      float* __restrict__ out,
                      int B, int D)
{
    const int b = blockIdx.x;
    const int c = threadIdx.x * 4;   // float4 column owned by this thread

    float4 s = make_float4(0.f, 0.f, 0.f, 0.f);
    if (c < D) {
#pragma unroll
        for (int t = 0; t < TSPLIT; t++) {
            const float4 v = *(const float4*)&g_part[((size_t)t * B + b) * (size_t)D + c];
            s.x += v.x; s.y += v.y; s.z += v.z; s.w += v.w;
        }
        const float inv = 1.0f / (float)(plen[b] - ilen[b]);
        s.x *= inv; s.y *= inv; s.z *= inv; s.w *= inv;
    }

    // block-reduce sum of squares of the mean vector
    float ss = s.x * s.x + s.y * s.y + s.z * s.z + s.w * s.w;
    __shared__ float sm[32];
    for (int off = 16; off > 0; off >>= 1)
        ss += __shfl_down_sync(0xFFFFFFFFu, ss, off);
    const int lane = threadIdx.x & 31, wid = threadIdx.x >> 5;
    if (lane == 0) sm[wid] = ss;
    __syncthreads();
    const int nwarps = (blockDim.x + 31) >> 5;
    if (wid == 0) {
        float v = (lane < nwarps) ? sm[lane] : 0.f;
        for (int off = 16; off > 0; off >>= 1)
            v += __shfl_down_sync(0xFFFFFFFFu, v, off);
        if (lane == 0) sm[0] = v;
    }
    __syncthreads();

    const float norm = fmaxf(sqrtf(sm[0]), 1e-12f);
    const float inv_n = 1.0f / norm;

    if (c < D) {
        s.x *= inv_n; s.y *= inv_n; s.z *= inv_n; s.w *= inv_n;
        *(float4*)(out + (size_t)b * D + c) = s;
    }
}

// ---------------------------------------------------------------------------
extern "C" void kernel_launch(void* const* d_in, const int* in_sizes, int n_in,
                              void* d_out, int out_size)
{
    const float* hs   = (const float*)d_in[0];
    const int*   plen = (const int*)d_in[1];
    const int*   ilen = (const int*)d_in[2];
    float*       out  = (float*)d_out;

    const int B = in_sizes[1];
    const int D = out_size / B;   // 4096

    // Stage 1: partial sums (memory-wall bound)
    dim3 grid1((D + 1023) / 1024, B, TSPLIT);
    pool_partial_kernel<<<grid1, 256>>>(hs, plen, ilen, B, D);

    // Stage 2: fused reduce + mean + L2 normalize
    int threads = D / 4;            // 1024 for D=4096
    if (threads > 1024) threads = 1024;
    mean_norm_kernel<<<B, threads>>>(plen, ilen, out, B, D);
}

// round 3
// speedup vs baseline: 1.0723x; 1.0481x over previous
#include <cuda_runtime.h>
#include <cuda_bf16.h>
#include <math.h>

// ---------------------------------------------------------------------------
// GritLM pooling: masked segment mean over tokens + L2 normalize per sequence.
// Inputs (metadata order):
//   d_in[0] : float32 hidden_states [TOTAL, D]
//   d_in[1] : int32   prompt_lens   [B]
//   d_in[2] : int32   instruction_lens [B]
// Output: float32 [B, D]
//
// Stage 1: masked partial column sums (memory-wall bound).
// Stage 2: fused reduce + mean + L2 normalize (one kernel, B blocks).
// ---------------------------------------------------------------------------

#define TSPLIT 16
#define MAX_B 64
#define MAX_D 8192
// Partial-sum scratch (static device allocation; runtime allocs forbidden).
__device__ float g_part[(size_t)TSPLIT * MAX_B * MAX_D];

__device__ __forceinline__ float4 ldcs4(const float* p) {
    return __ldcs((const float4*)p);
}

// ---------------------------------------------------------------------------
// Kernel 1: partial masked column sums.
// grid: (ceil(D/1024), B, TSPLIT), block: 256 threads.
// Each thread owns a float4 column strip; accumulates rows
// [start + r0, start + r1) with r < instruction_len rows excluded.
// 8x row unroll -> 8 outstanding LDG.128 per thread (deep MLP).
// ---------------------------------------------------------------------------
__global__ __launch_bounds__(256, 8)
void pool_partial_kernel(const float* __restrict__ hs,
                         const int* __restrict__ plen,
                         const int* __restrict__ ilen,
                         int B, int D)
{
    const int b     = blockIdx.y;
    const int split = blockIdx.z;
    const int c0    = blockIdx.x * 1024 + threadIdx.x * 4;

    // starts = exclusive prefix sum of prompt_lens (B is tiny)
    long long start = 0;
    for (int i = 0; i < b; i++) start += (long long)plen[i];
    const int len  = plen[b];
    const int inst = ilen[b];

    const int chunk = (len + TSPLIT - 1) / TSPLIT;
    int r0 = split * chunk;
    int r1 = r0 + chunk; if (r1 > len) r1 = len;
    if (r0 < inst) r0 = inst;        // mask instruction tokens

    float4 acc0 = make_float4(0.f, 0.f, 0.f, 0.f);
    float4 acc1 = make_float4(0.f, 0.f, 0.f, 0.f);

    if (c0 < D && r0 < r1) {
        const float* base = hs + (start + (long long)r0) * (long long)D + c0;
        const long long stride = D;
        int r = r0;
        // 8x row unroll -> MLP=8 independent LDG.128 per thread
        for (; r + 7 < r1; r += 8) {
            float4 v0 = ldcs4(base);
            float4 v1 = ldcs4(base + stride);
            float4 v2 = ldcs4(base + 2 * stride);
            float4 v3 = ldcs4(base + 3 * stride);
            float4 v4 = ldcs4(base + 4 * stride);
            float4 v5 = ldcs4(base + 5 * stride);
            float4 v6 = ldcs4(base + 6 * stride);
            float4 v7 = ldcs4(base + 7 * stride);
            acc0.x += v0.x + v1.x + v2.x + v3.x;
            acc0.y += v0.y + v1.y + v2.y + v3.y;
            acc0.z += v0.z + v1.z + v2.z + v3.z;
            acc0.w += v0.w + v1.w + v2.w + v3.w;
            acc1.x += v4.x + v5.x + v6.x + v7.x;
            acc1.y += v4.y + v5.y + v6.y + v7.y;
            acc1.z += v4.z + v5.z + v6.z + v7.z;
            acc1.w += v4.w + v5.w + v6.w + v7.w;
            base += 8 * stride;
        }
        for (; r < r1; r++) {
            float4 v = ldcs4(base);
            acc0.x += v.x; acc0.y += v.y; acc0.z += v.z; acc0.w += v.w;
            base += stride;
        }
    }

    if (c0 < D) {
        acc0.x += acc1.x; acc0.y += acc1.y; acc0.z += acc1.z; acc0.w += acc1.w;
        float* p = &g_part[((size_t)split * B + b) * (size_t)D + c0];
        *(float4*)p = acc0;
    }
}

// ---------------------------------------------------------------------------
// Kernel 2 (fused): reduce TSPLIT partials -> mean -> L2 normalize -> out.
// One block per sequence; blockDim.x == D/4 (one float4 per thread, D<=4096).
// ---------------------------------------------------------------------------
__global__ __launch_bounds__(1024)
void mean_norm_kernel(const int* __restrict__ plen,
                      const int* __restrict__ ilen,
                      float* __restrict__ out,
                      int B, int D)
{
    const int b = blockIdx.x;
    const int c = threadIdx.x * 4;   // float4 column owned by this thread

    float4 s = make_float4(0.f, 0.f, 0.f, 0.f);
    if (c < D) {
#pragma unroll
        for (int t = 0; t < TSPLIT; t++) {
            const float4 v = *(const float4*)&g_part[((size_t)t * B + b) * (size_t)D + c];
            s.x += v.x; s.y += v.y; s.z += v.z; s.w += v.w;
        }
        const float inv = 1.0f / (float)(plen[b] - ilen[b]);
        s.x *= inv; s.y *= inv; s.z *= inv; s.w *= inv;
    }

    // block-reduce sum of squares of the mean vector
    float ss = s.x * s.x + s.y * s.y + s.z * s.z + s.w * s.w;
    __shared__ float sm[32];
    for (int off = 16; off > 0; off >>= 1)
        ss += __shfl_down_sync(0xFFFFFFFFu, ss, off);
    const int lane = threadIdx.x & 31, wid = threadIdx.x >> 5;
    if (lane == 0) sm[wid] = ss;
    __syncthreads();
    const int nwarps = (blockDim.x + 31) >> 5;
    if (wid == 0) {
        float v = (lane < nwarps) ? sm[lane] : 0.f;
        for (int off = 16; off > 0; off >>= 1)
            v += __shfl_down_sync(0xFFFFFFFFu, v, off);
        if (lane == 0) sm[0] = v;
    }
    __syncthreads();

    const float norm = fmaxf(sqrtf(sm[0]), 1e-12f);
    const float inv_n = 1.0f / norm;

    if (c < D) {
        s.x *= inv_n; s.y *= inv_n; s.z *= inv_n; s.w *= inv_n;
        *(float4*)(out + (size_t)b * D + c) = s;
    }
}

// ---------------------------------------------------------------------------
extern "C" void kernel_launch(void* const* d_in, const int* in_sizes, int n_in,
                              void* d_out, int out_size)
{
    const float* hs   = (const float*)d_in[0];
    const int*   plen = (const int*)d_in[1];
    const int*   ilen = (const int*)d_in[2];
    float*       out  = (float*)d_out;

    const int B = in_sizes[1];
    const int D = out_size / B;   // 4096

    // Stage 1: partial sums (memory-wall bound)
    dim3 grid1((D + 1023) / 1024, B, TSPLIT);
    pool_partial_kernel<<<grid1, 256>>>(hs, plen, ilen, B, D);

    // Stage 2: fused reduce + mean + L2 normalize
    int threads = D / 4;            // 1024 for D=4096
    if (threads > 1024) threads = 1024;
    mean_norm_kernel<<<B, threads>>>(plen, ilen, out, B, D);
}